// round 15
// baseline (speedup 1.0000x reference)
#include <cuda_runtime.h>
#include <cuda_fp16.h>
#include <cstdint>
#include <cstddef>

// Problem constants (fixed by setup_inputs)
#define Bn 4
#define Sn 2048
#define Dn 1024
#define Hn 16
#define HDn 64
#define NBLK 8
#define BLKS 256

#define GK 1024            // pure fp16 GEMM: K = D
#define GM 8192            // B*S
#define GN 2048            // q rows then k rows
#define NCH (GK / 32)      // 32 K-chunks of 32

// ---------------------------------------------------------------------------
// Device scratch (allocation-free per harness rules)
// ---------------------------------------------------------------------------
__device__ __align__(256) __half g_A[(size_t)GM * GK];   // 16 MB
__device__ __align__(256) __half g_W[(size_t)GN * GK];   //  4 MB
// head-major projected Q (pre-scaled by 1/8) and K, fp16
__device__ __align__(256) __half g_Qh[(size_t)Bn * Hn * Sn * HDn];  // 16 MB
__device__ __align__(256) __half g_Kh[(size_t)Bn * Hn * Sn * HDn];

// ---------------------------------------------------------------------------
// Baseline-PTX helpers (no sm_103a-only features — harness targets compute_103)
// ---------------------------------------------------------------------------
__device__ __forceinline__ uint32_t smem_u32(const void* p) {
    uint32_t a;
    asm("{ .reg .u64 t; cvta.to.shared.u64 t, %1; cvt.u32.u64 %0, t; }"
        : "=r"(a) : "l"(p));
    return a;
}
__device__ __forceinline__ void cp16(uint32_t dst, const void* src) {
    asm volatile("cp.async.cg.shared.global [%0], [%1], 16;" :: "r"(dst), "l"(src));
}
#define CP_COMMIT() asm volatile("cp.async.commit_group;" ::: "memory")
#define CP_WAIT2()  asm volatile("cp.async.wait_group 2;" ::: "memory")
#define CP_WAIT1()  asm volatile("cp.async.wait_group 1;" ::: "memory")
#define CP_WAIT0()  asm volatile("cp.async.wait_group 0;" ::: "memory")

#define LDSM_X4(r, addr) \
    asm volatile("ldmatrix.sync.aligned.m8n8.x4.shared.b16 {%0,%1,%2,%3}, [%4];" \
        : "=r"((r)[0]), "=r"((r)[1]), "=r"((r)[2]), "=r"((r)[3]) : "r"(addr))

__device__ __forceinline__ void mma_f16(float* c, const uint32_t* a,
                                        const uint32_t* b) {
    asm volatile(
        "mma.sync.aligned.m16n8k16.row.col.f32.f16.f16.f32 "
        "{%0,%1,%2,%3}, {%4,%5,%6,%7}, {%8,%9}, {%0,%1,%2,%3};"
        : "+f"(c[0]), "+f"(c[1]), "+f"(c[2]), "+f"(c[3])
        : "r"(a[0]), "r"(a[1]), "r"(a[2]), "r"(a[3]), "r"(b[0]), "r"(b[1]));
}

// ---------------------------------------------------------------------------
// Fused cast kernel:
//   blocks [0, 4096):    x -> fp16 g_A
//   blocks [4096, 5120): wq/wk -> fp16 g_W
// ---------------------------------------------------------------------------
__device__ __forceinline__ uint32_t pk2h(__half a, __half b) {
    return (uint32_t)__half_as_ushort(a) | ((uint32_t)__half_as_ushort(b) << 16);
}

__global__ __launch_bounds__(256) void cast_all(const float* __restrict__ x,
                                                const float* __restrict__ wq,
                                                const float* __restrict__ wk) {
    const int blk = blockIdx.x;
    if (blk < 4096) {
        size_t i = ((size_t)blk * 256 + threadIdx.x) * 8;
        float4 v0 = *(const float4*)(x + i);
        float4 v1 = *(const float4*)(x + i + 4);
        float v[8] = {v0.x, v0.y, v0.z, v0.w, v1.x, v1.y, v1.z, v1.w};
        __half h[8];
        #pragma unroll
        for (int e = 0; e < 8; e++) h[e] = __float2half(v[e]);
        uint4 H = {pk2h(h[0], h[1]), pk2h(h[2], h[3]),
                   pk2h(h[4], h[5]), pk2h(h[6], h[7])};
        *(uint4*)(g_A + i) = H;
    } else {
        size_t i = ((size_t)(blk - 4096) * 256 + threadIdx.x) * 8;
        size_t n = i >> 10, k = i & 1023;
        const float* src = (n < 1024) ? (wq + n * 1024 + k)
                                      : (wk + (n - 1024) * 1024 + k);
        float4 v0 = *(const float4*)src;
        float4 v1 = *(const float4*)(src + 4);
        float v[8] = {v0.x, v0.y, v0.z, v0.w, v1.x, v1.y, v1.z, v1.w};
        __half h[8];
        #pragma unroll
        for (int e = 0; e < 8; e++) h[e] = __float2half(v[e]);
        uint4 H = {pk2h(h[0], h[1]), pk2h(h[2], h[3]),
                   pk2h(h[4], h[5]), pk2h(h[6], h[7])};
        *(uint4*)(g_W + i) = H;
    }
}

// ---------------------------------------------------------------------------
// mma.sync fp16 GEMM (mainloop FROZEN — at legacy-HMMA ceiling):
//   C = fp16(x) . fp16(w)^T (+bias), K=1024
//   CTA 128x128, K-chunk 32, 4-stage cp.async pipeline, 2 CTA/SM.
//   Ride-along (DRAM idle under HMMA): zero-fill this CTA's 64 KB slice of
//   the weight output + copy its 32 KB slice of x into the output tuple.
//   Epilogue: +bias; Q: *0.125; fp16 cast; head-major write.
// ---------------------------------------------------------------------------
#define RS 80                      // smem row stride bytes (32 fp16 + pad)
#define STAGE (128 * RS * 2)       // A(10240) + B(10240) = 20480
#define GEMM_SMEM (4 * STAGE)      // 81920

__global__ __launch_bounds__(256, 2) void gemm_tc(
    const float* __restrict__ bq, const float* __restrict__ bk,
    const float* __restrict__ x,  float* __restrict__ out_x,
    float* __restrict__ out_w,    int do_copy)
{
    extern __shared__ char smem[];
    const uint32_t smb = smem_u32(smem);
    const int tid  = threadIdx.x;
    const int wid  = tid >> 5;
    const int lane = tid & 31;
    const int mw = wid & 3;        // m warp (32 rows)
    const int nw = wid >> 2;       // n warp (64 cols)
    const int bn = blockIdx.x;     // 0..15
    const int bm = blockIdx.y;     // 0..63

    float c[2][8][4];
    #pragma unroll
    for (int mt = 0; mt < 2; mt++)
        #pragma unroll
        for (int nt = 0; nt < 8; nt++)
            #pragma unroll
            for (int e = 0; e < 4; e++) c[mt][nt][e] = 0.f;

    const uint32_t a_base = (uint32_t)((mw * 32 + (lane & 15)) * RS + (lane >> 4) * 16);
    const uint32_t b_base = (uint32_t)(128 * RS +
        (nw * 64 + ((lane >> 4) & 1) * 8 + (lane & 7)) * RS + ((lane >> 3) & 1) * 16);

    auto stage = [&](int slot, int kc) {
        const uint32_t sb = smb + slot * STAGE;
        const size_t koff = (size_t)kc * 32;
        #pragma unroll
        for (int i = 0; i < 4; i++) {
            const int idx = tid + i * 256;      // 0..1023
            const int row = idx >> 2, cc = idx & 3;
            if (row < 128) {
                cp16(sb + row * RS + cc * 16,
                     g_A + (size_t)(bm * 128 + row) * GK + koff + cc * 8);
            } else {
                const int r2 = row - 128;
                cp16(sb + 128 * RS + r2 * RS + cc * 16,
                     g_W + (size_t)(bn * 128 + r2) * GK + koff + cc * 8);
            }
        }
    };

    #pragma unroll
    for (int s = 0; s < 3; s++) { stage(s, s); CP_COMMIT(); }

    // Ride-along stores while the prologue cp.asyncs land: zero-fill the
    // weight output slice; copy the x slice into the output tuple.
    {
        const int cta = bm * 16 + bn;                // 0..1023
        const float4 z = {0.f, 0.f, 0.f, 0.f};
        float4* zw = (float4*)out_w + (size_t)cta * 4096;
        #pragma unroll
        for (int i = 0; i < 16; i++) zw[tid + i * 256] = z;
        if (do_copy) {
            const float4* src = (const float4*)x + (size_t)cta * 2048;
            float4* dst = (float4*)out_x + (size_t)cta * 2048;
            #pragma unroll
            for (int i = 0; i < 8; i++)
                dst[tid + i * 256] = src[tid + i * 256];
        }
    }

    for (int kc = 0; kc < NCH; kc++) {
        const uint32_t sb = smb + (kc & 3) * STAGE;
        CP_WAIT2();
        __syncthreads();
        if (kc + 3 < NCH) stage((kc + 3) & 3, kc + 3);
        CP_COMMIT();

        #pragma unroll
        for (int ks = 0; ks < 2; ks++) {
            uint32_t a0[4], a1[4], b0[4], b1[4], b2[4], b3[4];
            LDSM_X4(a0, sb + a_base + ks * 32);
            LDSM_X4(a1, sb + a_base + 16 * RS + ks * 32);
            LDSM_X4(b0, sb + b_base + ks * 32);
            LDSM_X4(b1, sb + b_base + 16 * RS + ks * 32);
            LDSM_X4(b2, sb + b_base + 32 * RS + ks * 32);
            LDSM_X4(b3, sb + b_base + 48 * RS + ks * 32);
            const uint32_t* bp[4] = {b0, b1, b2, b3};
            #pragma unroll
            for (int mt = 0; mt < 2; mt++) {
                const uint32_t* a = mt ? a1 : a0;
                #pragma unroll
                for (int nt = 0; nt < 8; nt++)
                    mma_f16(c[mt][nt], a, bp[nt >> 1] + (nt & 1) * 2);
            }
        }
    }

    // Epilogue: bias, (Q: *0.125), fp16 cast, head-major write
    const int nbase = (bn & 7) * 128 + nw * 64 + (lane & 3) * 2;   // 0..1023
    const bool isQ = (bn < 8);
    const float* bias = isQ ? bq : bk;
    __half* th = isQ ? g_Qh : g_Kh;
    const int hh = ((bn & 7) << 1) + nw;           // head (constant per thread)
    const float scl = isQ ? 0.125f : 1.0f;
    float2 bv[8];
    #pragma unroll
    for (int nt = 0; nt < 8; nt++)
        bv[nt] = *(const float2*)(bias + nbase + nt * 8);

    #pragma unroll
    for (int mt = 0; mt < 2; mt++) {
        #pragma unroll
        for (int h2 = 0; h2 < 2; h2++) {
            const int m = bm * 128 + mw * 32 + mt * 16 + h2 * 8 + (lane >> 2);
            const int bb = m >> 11, ss = m & 2047;
            const size_t rowoff = ((size_t)(bb * Hn + hh) * Sn + ss) * HDn
                                + (lane & 3) * 2;
            #pragma unroll
            for (int nt = 0; nt < 8; nt++) {
                float v0 = (c[mt][nt][h2 * 2 + 0] + bv[nt].x) * scl;
                float v1 = (c[mt][nt][h2 * 2 + 1] + bv[nt].y) * scl;
                *(__half2*)(th + rowoff + nt * 8) =
                    __halves2half2(__float2half(v0), __float2half(v1));
            }
        }
    }
}

// ---------------------------------------------------------------------------
// Tensor-core block-diagonal attention, 1-term scores (s = q_h . k_h):
//   CTA = 64 q rows x 256 keys x 8 HEADS (head-split), 256 threads / 8 warps.
//   grid (8, 8, 4): x -> (qc = x&3, head segment = x>>2) = 256 CTAs.
//   Two CTAs per output tile each accumulate 8 of 16 heads and combine via
//   atomicAdd (exactly 2 commutative addends -> deterministic). gemm_tc
//   zero-fills all of out_w first (same stream), so RED lands on zeros.
//   2 CTAs/SM co-residency hides exp/reduce latency under the sibling's MMA.
// ---------------------------------------------------------------------------
#define KHI 0
#define QHI 32768
#define ABUF 40960
#define SUMO (2 * ABUF)                       // row-sum scratch
#define ATTN_SMEM (SUMO + 4 * 64 * 4)         // 82,944

__global__ __launch_bounds__(256, 2) void attn_tc(float* __restrict__ out_w)
{
    extern __shared__ char smem[];
    const uint32_t smb = smem_u32(smem);
    float* sums = (float*)(smem + SUMO);

    const int tid  = threadIdx.x;
    const int wid  = tid >> 5;
    const int lane = tid & 31;
    const int nw = wid & 3;        // n warp: 64 keys
    const int mw = wid >> 2;       // m warp: 32 q rows
    const int b = blockIdx.z, blk = blockIdx.y;
    const int qc   = blockIdx.x & 3;           // 0..3
    const int h0   = (blockIdx.x >> 2) * 8;    // head segment: 0 or 8
    const int srow = blk * BLKS + qc * 64;     // first q row (within batch)
    const int krow = blk * BLKS;               // first key row

    auto stage = [&](int buf, int h) {
        const size_t kbase = ((size_t)(b * Hn + h) * Sn + krow) * HDn;
        const size_t qbase = ((size_t)(b * Hn + h) * Sn + srow) * HDn;
        const uint32_t sb = smb + buf * ABUF;
        #pragma unroll
        for (int it = 0; it < 8; it++) {
            const int idx = tid + it * 256;          // 0..2047
            const int row = idx >> 3, ch = idx & 7;
            const uint32_t d = (uint32_t)(row * 128 + ((ch ^ (row & 7)) << 4));
            cp16(sb + KHI + d, g_Kh + kbase + row * HDn + ch * 8);
        }
        #pragma unroll
        for (int it = 0; it < 2; it++) {
            const int idx = tid + it * 256;          // 0..511
            const int row = idx >> 3, ch = idx & 7;
            const uint32_t d = (uint32_t)(row * 128 + ((ch ^ (row & 7)) << 4));
            cp16(sb + QHI + d, g_Qh + qbase + row * HDn + ch * 8);
        }
    };

    stage(0, h0); CP_COMMIT();

    float acc[2][8][4];
    #pragma unroll
    for (int mt = 0; mt < 2; mt++)
        #pragma unroll
        for (int nt = 0; nt < 8; nt++)
            #pragma unroll
            for (int e = 0; e < 4; e++) acc[mt][nt][e] = 0.f;

    for (int hi = 0; hi < 8; hi++) {
        if (hi + 1 < 8) { stage((hi + 1) & 1, h0 + hi + 1); CP_COMMIT(); CP_WAIT1(); }
        else            { CP_WAIT0(); }
        __syncthreads();
        const uint32_t sb = smb + (hi & 1) * ABUF;

        float c[2][8][4];
        #pragma unroll
        for (int mt = 0; mt < 2; mt++)
            #pragma unroll
            for (int nt = 0; nt < 8; nt++)
                #pragma unroll
                for (int e = 0; e < 4; e++) c[mt][nt][e] = 0.f;

        #pragma unroll
        for (int ks = 0; ks < 4; ks++) {
            uint32_t a[2][4], bf[4][4];
            #pragma unroll
            for (int mt = 0; mt < 2; mt++) {
                const int row = mw * 32 + mt * 16 + (lane & 15);
                const int ci = 2 * ks + (lane >> 4);
                LDSM_X4(a[mt], sb + QHI + row * 128 + ((ci ^ (row & 7)) << 4));
            }
            #pragma unroll
            for (int nb = 0; nb < 4; nb++) {
                const int r = nw * 64 + nb * 16 + ((lane >> 4) & 1) * 8 + (lane & 7);
                const int ci = 2 * ks + ((lane >> 3) & 1);
                LDSM_X4(bf[nb], sb + KHI + r * 128 + ((ci ^ (r & 7)) << 4));
            }
            #pragma unroll
            for (int mt = 0; mt < 2; mt++)
                #pragma unroll
                for (int nt = 0; nt < 8; nt++)
                    mma_f16(c[mt][nt], a[mt], bf[nt >> 1] + (nt & 1) * 2);
        }

        // exp (scores pre-scaled via Q; no max-sub needed, |s| <~ 6)
        #pragma unroll
        for (int mt = 0; mt < 2; mt++)
            #pragma unroll
            for (int nt = 0; nt < 8; nt++)
                #pragma unroll
                for (int e = 0; e < 4; e++) c[mt][nt][e] = __expf(c[mt][nt][e]);

        // per-row partial sums over this warp's 64 keys -> smem
        #pragma unroll
        for (int mt = 0; mt < 2; mt++) {
            #pragma unroll
            for (int h2 = 0; h2 < 2; h2++) {
                float p = 0.f;
                #pragma unroll
                for (int nt = 0; nt < 8; nt++)
                    p += c[mt][nt][h2 * 2] + c[mt][nt][h2 * 2 + 1];
                p += __shfl_xor_sync(0xffffffffu, p, 1);
                p += __shfl_xor_sync(0xffffffffu, p, 2);
                const int lr = mw * 32 + mt * 16 + h2 * 8 + (lane >> 2);
                if ((lane & 3) == 0) sums[nw * 64 + lr] = p;
            }
        }
        __syncthreads();

        #pragma unroll
        for (int mt = 0; mt < 2; mt++) {
            #pragma unroll
            for (int h2 = 0; h2 < 2; h2++) {
                const int lr = mw * 32 + mt * 16 + h2 * 8 + (lane >> 2);
                const float denom = sums[lr] + sums[64 + lr]
                                  + sums[128 + lr] + sums[192 + lr];
                const float inv = (1.f / 16.f) / denom;
                #pragma unroll
                for (int nt = 0; nt < 8; nt++) {
                    acc[mt][nt][h2 * 2]     += c[mt][nt][h2 * 2] * inv;
                    acc[mt][nt][h2 * 2 + 1] += c[mt][nt][h2 * 2 + 1] * inv;
                }
            }
        }
    }

    // Combine the two head-segments via RED.ADD (out_w pre-zeroed by gemm_tc;
    // exactly two commutative fp32 addends per element -> deterministic).
    #pragma unroll
    for (int mt = 0; mt < 2; mt++) {
        #pragma unroll
        for (int h2 = 0; h2 < 2; h2++) {
            const int lr = mw * 32 + mt * 16 + h2 * 8 + (lane >> 2);
            const size_t base = ((size_t)(b * Sn + srow + lr)) * Sn
                              + blk * BLKS + nw * 64 + (lane & 3) * 2;
            #pragma unroll
            for (int nt = 0; nt < 8; nt++) {
                atomicAdd(out_w + base + nt * 8,     acc[mt][nt][h2 * 2]);
                atomicAdd(out_w + base + nt * 8 + 1, acc[mt][nt][h2 * 2 + 1]);
            }
        }
    }
}

// ---------------------------------------------------------------------------
extern "C" void kernel_launch(void* const* d_in, const int* in_sizes, int n_in,
                              void* d_out, int out_size)
{
    const float* x  = (const float*)d_in[0];
    const float* wq = (const float*)d_in[1];
    const float* wk = (const float*)d_in[2];
    const float* bq = (const float*)d_in[3];
    const float* bk = (const float*)d_in[4];
    float* out = (float*)d_out;

    const size_t x_elems = (size_t)Bn * Sn * Dn;   //  8,388,608
    const size_t w_elems = (size_t)Bn * Sn * Sn;   // 16,777,216

    float* out_w;
    int do_copy;
    if ((size_t)out_size >= x_elems + w_elems) {
        out_w = out + x_elems;
        do_copy = 1;
    } else {
        out_w = out;
        do_copy = 0;
    }

    // fp16 casts
    cast_all<<<5120, 256>>>(x, wq, wk);

    // mma.sync fp16 projection GEMM (128x128, 2 CTA/SM, K=1024)
    // + ride-along zero-fill of out_w and x->out copy under idle DRAM
    cudaFuncSetAttribute(gemm_tc, cudaFuncAttributeMaxDynamicSharedMemorySize,
                         GEMM_SMEM);
    dim3 ggrid(16, 64);
    gemm_tc<<<ggrid, 256, GEMM_SMEM>>>(bq, bk, x, out, out_w, do_copy);

    // tensor-core block-diagonal attention, head-split (256 CTAs, 2/SM)
    cudaFuncSetAttribute(attn_tc, cudaFuncAttributeMaxDynamicSharedMemorySize,
                         ATTN_SMEM);
    dim3 agrid(8, NBLK, Bn);
    attn_tc<<<agrid, 256, ATTN_SMEM>>>(out_w);
}

// round 16
// speedup vs baseline: 1.0777x; 1.0777x over previous
#include <cuda_runtime.h>
#include <cuda_fp16.h>
#include <cstdint>
#include <cstddef>

// Problem constants (fixed by setup_inputs)
#define Bn 4
#define Sn 2048
#define Dn 1024
#define Hn 16
#define HDn 64
#define NBLK 8
#define BLKS 256

#define GK 1024            // pure fp16 GEMM: K = D
#define GM 8192            // B*S
#define GN 2048            // q rows then k rows
#define NCH (GK / 32)      // 32 K-chunks of 32

// ---------------------------------------------------------------------------
// Device scratch (allocation-free per harness rules)
// ---------------------------------------------------------------------------
__device__ __align__(256) __half g_A[(size_t)GM * GK];   // 16 MB
__device__ __align__(256) __half g_W[(size_t)GN * GK];   //  4 MB
// head-major projected Q (pre-scaled by 1/8) and K, fp16
__device__ __align__(256) __half g_Qh[(size_t)Bn * Hn * Sn * HDn];  // 16 MB
__device__ __align__(256) __half g_Kh[(size_t)Bn * Hn * Sn * HDn];

// ---------------------------------------------------------------------------
// Baseline-PTX helpers (no sm_103a-only features — harness targets compute_103)
// ---------------------------------------------------------------------------
__device__ __forceinline__ uint32_t smem_u32(const void* p) {
    uint32_t a;
    asm("{ .reg .u64 t; cvta.to.shared.u64 t, %1; cvt.u32.u64 %0, t; }"
        : "=r"(a) : "l"(p));
    return a;
}
__device__ __forceinline__ void cp16(uint32_t dst, const void* src) {
    asm volatile("cp.async.cg.shared.global [%0], [%1], 16;" :: "r"(dst), "l"(src));
}
#define CP_COMMIT() asm volatile("cp.async.commit_group;" ::: "memory")
#define CP_WAIT2()  asm volatile("cp.async.wait_group 2;" ::: "memory")
#define CP_WAIT1()  asm volatile("cp.async.wait_group 1;" ::: "memory")
#define CP_WAIT0()  asm volatile("cp.async.wait_group 0;" ::: "memory")

#define LDSM_X4(r, addr) \
    asm volatile("ldmatrix.sync.aligned.m8n8.x4.shared.b16 {%0,%1,%2,%3}, [%4];" \
        : "=r"((r)[0]), "=r"((r)[1]), "=r"((r)[2]), "=r"((r)[3]) : "r"(addr))

__device__ __forceinline__ void mma_f16(float* c, const uint32_t* a,
                                        const uint32_t* b) {
    asm volatile(
        "mma.sync.aligned.m16n8k16.row.col.f32.f16.f16.f32 "
        "{%0,%1,%2,%3}, {%4,%5,%6,%7}, {%8,%9}, {%0,%1,%2,%3};"
        : "+f"(c[0]), "+f"(c[1]), "+f"(c[2]), "+f"(c[3])
        : "r"(a[0]), "r"(a[1]), "r"(a[2]), "r"(a[3]), "r"(b[0]), "r"(b[1]));
}

// ---------------------------------------------------------------------------
// Fused cast kernel, 16 floats/thread (MLP=4) for higher achieved HBM bw:
//   blocks [0, 2048):    x -> fp16 g_A
//   blocks [2048, 2560): wq/wk -> fp16 g_W
// ---------------------------------------------------------------------------
__device__ __forceinline__ uint32_t pk2h(__half a, __half b) {
    return (uint32_t)__half_as_ushort(a) | ((uint32_t)__half_as_ushort(b) << 16);
}

__device__ __forceinline__ uint4 cast8(const float4 v0, const float4 v1) {
    float v[8] = {v0.x, v0.y, v0.z, v0.w, v1.x, v1.y, v1.z, v1.w};
    __half h[8];
    #pragma unroll
    for (int e = 0; e < 8; e++) h[e] = __float2half(v[e]);
    uint4 H = {pk2h(h[0], h[1]), pk2h(h[2], h[3]),
               pk2h(h[4], h[5]), pk2h(h[6], h[7])};
    return H;
}

__global__ __launch_bounds__(256) void cast_all(const float* __restrict__ x,
                                                const float* __restrict__ wq,
                                                const float* __restrict__ wk) {
    const int blk = blockIdx.x;
    if (blk < 2048) {
        size_t i = ((size_t)blk * 256 + threadIdx.x) * 16;
        float4 v0 = *(const float4*)(x + i);
        float4 v1 = *(const float4*)(x + i + 4);
        float4 v2 = *(const float4*)(x + i + 8);
        float4 v3 = *(const float4*)(x + i + 12);
        *(uint4*)(g_A + i)     = cast8(v0, v1);
        *(uint4*)(g_A + i + 8) = cast8(v2, v3);
    } else {
        size_t i = ((size_t)(blk - 2048) * 256 + threadIdx.x) * 16;
        size_t n = i >> 10, k = i & 1023;
        const float* src = (n < 1024) ? (wq + n * 1024 + k)
                                      : (wk + (n - 1024) * 1024 + k);
        float4 v0 = *(const float4*)src;
        float4 v1 = *(const float4*)(src + 4);
        float4 v2 = *(const float4*)(src + 8);
        float4 v3 = *(const float4*)(src + 12);
        *(uint4*)(g_W + i)     = cast8(v0, v1);
        *(uint4*)(g_W + i + 8) = cast8(v2, v3);
    }
}

// ---------------------------------------------------------------------------
// mma.sync fp16 GEMM (mainloop FROZEN — at legacy-HMMA ceiling):
//   C = fp16(x) . fp16(w)^T (+bias), K=1024
//   CTA 128x128, K-chunk 32, 4-stage cp.async pipeline, 2 CTA/SM.
//   Ride-along (DRAM idle under HMMA): zero-fill this CTA's 64 KB slice of
//   the weight output + copy its 32 KB slice of x into the output tuple.
//   Epilogue: +bias; Q: *0.125; fp16 cast; head-major write.
// ---------------------------------------------------------------------------
#define RS 80                      // smem row stride bytes (32 fp16 + pad)
#define STAGE (128 * RS * 2)       // A(10240) + B(10240) = 20480
#define GEMM_SMEM (4 * STAGE)      // 81920

__global__ __launch_bounds__(256, 2) void gemm_tc(
    const float* __restrict__ bq, const float* __restrict__ bk,
    const float* __restrict__ x,  float* __restrict__ out_x,
    float* __restrict__ out_w,    int do_copy)
{
    extern __shared__ char smem[];
    const uint32_t smb = smem_u32(smem);
    const int tid  = threadIdx.x;
    const int wid  = tid >> 5;
    const int lane = tid & 31;
    const int mw = wid & 3;        // m warp (32 rows)
    const int nw = wid >> 2;       // n warp (64 cols)
    const int bn = blockIdx.x;     // 0..15
    const int bm = blockIdx.y;     // 0..63

    float c[2][8][4];
    #pragma unroll
    for (int mt = 0; mt < 2; mt++)
        #pragma unroll
        for (int nt = 0; nt < 8; nt++)
            #pragma unroll
            for (int e = 0; e < 4; e++) c[mt][nt][e] = 0.f;

    const uint32_t a_base = (uint32_t)((mw * 32 + (lane & 15)) * RS + (lane >> 4) * 16);
    const uint32_t b_base = (uint32_t)(128 * RS +
        (nw * 64 + ((lane >> 4) & 1) * 8 + (lane & 7)) * RS + ((lane >> 3) & 1) * 16);

    auto stage = [&](int slot, int kc) {
        const uint32_t sb = smb + slot * STAGE;
        const size_t koff = (size_t)kc * 32;
        #pragma unroll
        for (int i = 0; i < 4; i++) {
            const int idx = tid + i * 256;      // 0..1023
            const int row = idx >> 2, cc = idx & 3;
            if (row < 128) {
                cp16(sb + row * RS + cc * 16,
                     g_A + (size_t)(bm * 128 + row) * GK + koff + cc * 8);
            } else {
                const int r2 = row - 128;
                cp16(sb + 128 * RS + r2 * RS + cc * 16,
                     g_W + (size_t)(bn * 128 + r2) * GK + koff + cc * 8);
            }
        }
    };

    #pragma unroll
    for (int s = 0; s < 3; s++) { stage(s, s); CP_COMMIT(); }

    // Ride-along stores while the prologue cp.asyncs land: zero-fill the
    // weight output slice; copy the x slice into the output tuple.
    {
        const int cta = bm * 16 + bn;                // 0..1023
        const float4 z = {0.f, 0.f, 0.f, 0.f};
        float4* zw = (float4*)out_w + (size_t)cta * 4096;
        #pragma unroll
        for (int i = 0; i < 16; i++) zw[tid + i * 256] = z;
        if (do_copy) {
            const float4* src = (const float4*)x + (size_t)cta * 2048;
            float4* dst = (float4*)out_x + (size_t)cta * 2048;
            #pragma unroll
            for (int i = 0; i < 8; i++)
                dst[tid + i * 256] = src[tid + i * 256];
        }
    }

    for (int kc = 0; kc < NCH; kc++) {
        const uint32_t sb = smb + (kc & 3) * STAGE;
        CP_WAIT2();
        __syncthreads();
        if (kc + 3 < NCH) stage((kc + 3) & 3, kc + 3);
        CP_COMMIT();

        #pragma unroll
        for (int ks = 0; ks < 2; ks++) {
            uint32_t a0[4], a1[4], b0[4], b1[4], b2[4], b3[4];
            LDSM_X4(a0, sb + a_base + ks * 32);
            LDSM_X4(a1, sb + a_base + 16 * RS + ks * 32);
            LDSM_X4(b0, sb + b_base + ks * 32);
            LDSM_X4(b1, sb + b_base + 16 * RS + ks * 32);
            LDSM_X4(b2, sb + b_base + 32 * RS + ks * 32);
            LDSM_X4(b3, sb + b_base + 48 * RS + ks * 32);
            const uint32_t* bp[4] = {b0, b1, b2, b3};
            #pragma unroll
            for (int mt = 0; mt < 2; mt++) {
                const uint32_t* a = mt ? a1 : a0;
                #pragma unroll
                for (int nt = 0; nt < 8; nt++)
                    mma_f16(c[mt][nt], a, bp[nt >> 1] + (nt & 1) * 2);
            }
        }
    }

    // Epilogue: bias, (Q: *0.125), fp16 cast, head-major write
    const int nbase = (bn & 7) * 128 + nw * 64 + (lane & 3) * 2;   // 0..1023
    const bool isQ = (bn < 8);
    const float* bias = isQ ? bq : bk;
    __half* th = isQ ? g_Qh : g_Kh;
    const int hh = ((bn & 7) << 1) + nw;           // head (constant per thread)
    const float scl = isQ ? 0.125f : 1.0f;
    float2 bv[8];
    #pragma unroll
    for (int nt = 0; nt < 8; nt++)
        bv[nt] = *(const float2*)(bias + nbase + nt * 8);

    #pragma unroll
    for (int mt = 0; mt < 2; mt++) {
        #pragma unroll
        for (int h2 = 0; h2 < 2; h2++) {
            const int m = bm * 128 + mw * 32 + mt * 16 + h2 * 8 + (lane >> 2);
            const int bb = m >> 11, ss = m & 2047;
            const size_t rowoff = ((size_t)(bb * Hn + hh) * Sn + ss) * HDn
                                + (lane & 3) * 2;
            #pragma unroll
            for (int nt = 0; nt < 8; nt++) {
                float v0 = (c[mt][nt][h2 * 2 + 0] + bv[nt].x) * scl;
                float v1 = (c[mt][nt][h2 * 2 + 1] + bv[nt].y) * scl;
                *(__half2*)(th + rowoff + nt * 8) =
                    __halves2half2(__float2half(v0), __float2half(v1));
            }
        }
    }
}

// ---------------------------------------------------------------------------
// Tensor-core block-diagonal attention (R14-validated FINAL form):
//   1-term scores (s = q_h . k_h), CTA = 64 q rows x 256 keys, 256 threads /
//   8 warps (2m x 4n, tile 32x64), grid (4 q-chunks, 8 blocks, 4 batches).
//   Fragments only — zero-fill and x-copy live in gemm_tc.
// ---------------------------------------------------------------------------
#define KHI 0
#define QHI 32768
#define ABUF 40960
#define SUMO (2 * ABUF)                       // row-sum scratch
#define ATTN_SMEM (SUMO + 4 * 64 * 4)         // 82,944

__global__ __launch_bounds__(256, 1) void attn_tc(float* __restrict__ out_w)
{
    extern __shared__ char smem[];
    const uint32_t smb = smem_u32(smem);
    float* sums = (float*)(smem + SUMO);

    const int tid  = threadIdx.x;
    const int wid  = tid >> 5;
    const int lane = tid & 31;
    const int nw = wid & 3;        // n warp: 64 keys
    const int mw = wid >> 2;       // m warp: 32 q rows
    const int b = blockIdx.z, blk = blockIdx.y, qc = blockIdx.x;
    const int srow = blk * BLKS + qc * 64;     // first q row (within batch)
    const int krow = blk * BLKS;               // first key row

    auto stage = [&](int buf, int h) {
        const size_t kbase = ((size_t)(b * Hn + h) * Sn + krow) * HDn;
        const size_t qbase = ((size_t)(b * Hn + h) * Sn + srow) * HDn;
        const uint32_t sb = smb + buf * ABUF;
        #pragma unroll
        for (int it = 0; it < 8; it++) {
            const int idx = tid + it * 256;          // 0..2047
            const int row = idx >> 3, ch = idx & 7;
            const uint32_t d = (uint32_t)(row * 128 + ((ch ^ (row & 7)) << 4));
            cp16(sb + KHI + d, g_Kh + kbase + row * HDn + ch * 8);
        }
        #pragma unroll
        for (int it = 0; it < 2; it++) {
            const int idx = tid + it * 256;          // 0..511
            const int row = idx >> 3, ch = idx & 7;
            const uint32_t d = (uint32_t)(row * 128 + ((ch ^ (row & 7)) << 4));
            cp16(sb + QHI + d, g_Qh + qbase + row * HDn + ch * 8);
        }
    };

    stage(0, 0); CP_COMMIT();

    float acc[2][8][4];
    #pragma unroll
    for (int mt = 0; mt < 2; mt++)
        #pragma unroll
        for (int nt = 0; nt < 8; nt++)
            #pragma unroll
            for (int e = 0; e < 4; e++) acc[mt][nt][e] = 0.f;

    for (int h = 0; h < Hn; h++) {
        if (h + 1 < Hn) { stage((h + 1) & 1, h + 1); CP_COMMIT(); CP_WAIT1(); }
        else            { CP_WAIT0(); }
        __syncthreads();
        const uint32_t sb = smb + (h & 1) * ABUF;

        float c[2][8][4];
        #pragma unroll
        for (int mt = 0; mt < 2; mt++)
            #pragma unroll
            for (int nt = 0; nt < 8; nt++)
                #pragma unroll
                for (int e = 0; e < 4; e++) c[mt][nt][e] = 0.f;

        #pragma unroll
        for (int ks = 0; ks < 4; ks++) {
            uint32_t a[2][4], bf[4][4];
            #pragma unroll
            for (int mt = 0; mt < 2; mt++) {
                const int row = mw * 32 + mt * 16 + (lane & 15);
                const int ci = 2 * ks + (lane >> 4);
                LDSM_X4(a[mt], sb + QHI + row * 128 + ((ci ^ (row & 7)) << 4));
            }
            #pragma unroll
            for (int nb = 0; nb < 4; nb++) {
                const int r = nw * 64 + nb * 16 + ((lane >> 4) & 1) * 8 + (lane & 7);
                const int ci = 2 * ks + ((lane >> 3) & 1);
                LDSM_X4(bf[nb], sb + KHI + r * 128 + ((ci ^ (r & 7)) << 4));
            }
            #pragma unroll
            for (int mt = 0; mt < 2; mt++)
                #pragma unroll
                for (int nt = 0; nt < 8; nt++)
                    mma_f16(c[mt][nt], a[mt], bf[nt >> 1] + (nt & 1) * 2);
        }

        // exp (scores pre-scaled via Q; no max-sub needed, |s| <~ 6)
        #pragma unroll
        for (int mt = 0; mt < 2; mt++)
            #pragma unroll
            for (int nt = 0; nt < 8; nt++)
                #pragma unroll
                for (int e = 0; e < 4; e++) c[mt][nt][e] = __expf(c[mt][nt][e]);

        // per-row partial sums over this warp's 64 keys -> smem
        #pragma unroll
        for (int mt = 0; mt < 2; mt++) {
            #pragma unroll
            for (int h2 = 0; h2 < 2; h2++) {
                float p = 0.f;
                #pragma unroll
                for (int nt = 0; nt < 8; nt++)
                    p += c[mt][nt][h2 * 2] + c[mt][nt][h2 * 2 + 1];
                p += __shfl_xor_sync(0xffffffffu, p, 1);
                p += __shfl_xor_sync(0xffffffffu, p, 2);
                const int lr = mw * 32 + mt * 16 + h2 * 8 + (lane >> 2);
                if ((lane & 3) == 0) sums[nw * 64 + lr] = p;
            }
        }
        __syncthreads();

        #pragma unroll
        for (int mt = 0; mt < 2; mt++) {
            #pragma unroll
            for (int h2 = 0; h2 < 2; h2++) {
                const int lr = mw * 32 + mt * 16 + h2 * 8 + (lane >> 2);
                const float denom = sums[lr] + sums[64 + lr]
                                  + sums[128 + lr] + sums[192 + lr];
                const float inv = (1.f / 16.f) / denom;
                #pragma unroll
                for (int nt = 0; nt < 8; nt++) {
                    acc[mt][nt][h2 * 2]     += c[mt][nt][h2 * 2] * inv;
                    acc[mt][nt][h2 * 2 + 1] += c[mt][nt][h2 * 2 + 1] * inv;
                }
            }
        }
    }

    // fragment store: out_w[b][srow+lr][blk*256 + nw*64 + nt*8 + (lane&3)*2]
    #pragma unroll
    for (int mt = 0; mt < 2; mt++) {
        #pragma unroll
        for (int h2 = 0; h2 < 2; h2++) {
            const int lr = mw * 32 + mt * 16 + h2 * 8 + (lane >> 2);
            const size_t base = ((size_t)(b * Sn + srow + lr)) * Sn
                              + blk * BLKS + nw * 64 + (lane & 3) * 2;
            #pragma unroll
            for (int nt = 0; nt < 8; nt++) {
                float2 v = {acc[mt][nt][h2 * 2], acc[mt][nt][h2 * 2 + 1]};
                *(float2*)(out_w + base + nt * 8) = v;
            }
        }
    }
}

// ---------------------------------------------------------------------------
extern "C" void kernel_launch(void* const* d_in, const int* in_sizes, int n_in,
                              void* d_out, int out_size)
{
    const float* x  = (const float*)d_in[0];
    const float* wq = (const float*)d_in[1];
    const float* wk = (const float*)d_in[2];
    const float* bq = (const float*)d_in[3];
    const float* bk = (const float*)d_in[4];
    float* out = (float*)d_out;

    const size_t x_elems = (size_t)Bn * Sn * Dn;   //  8,388,608
    const size_t w_elems = (size_t)Bn * Sn * Sn;   // 16,777,216

    float* out_w;
    int do_copy;
    if ((size_t)out_size >= x_elems + w_elems) {
        out_w = out + x_elems;
        do_copy = 1;
    } else {
        out_w = out;
        do_copy = 0;
    }

    // fp16 casts (16 floats/thread, MLP=4)
    cast_all<<<2560, 256>>>(x, wq, wk);

    // mma.sync fp16 projection GEMM (128x128, 2 CTA/SM, K=1024)
    // + ride-along zero-fill of out_w and x->out copy under idle DRAM
    cudaFuncSetAttribute(gemm_tc, cudaFuncAttributeMaxDynamicSharedMemorySize,
                         GEMM_SMEM);
    dim3 ggrid(16, 64);
    gemm_tc<<<ggrid, 256, GEMM_SMEM>>>(bq, bk, x, out, out_w, do_copy);

    // tensor-core block-diagonal attention (fragments only)
    cudaFuncSetAttribute(attn_tc, cudaFuncAttributeMaxDynamicSharedMemorySize,
                         ATTN_SMEM);
    dim3 agrid(4, NBLK, Bn);
    attn_tc<<<agrid, 256, ATTN_SMEM>>>(out_w);
}

// round 17
// speedup vs baseline: 1.0779x; 1.0002x over previous
#include <cuda_runtime.h>
#include <cuda_fp16.h>
#include <cstdint>
#include <cstddef>

// Problem constants (fixed by setup_inputs)
#define Bn 4
#define Sn 2048
#define Dn 1024
#define Hn 16
#define HDn 64
#define NBLK 8
#define BLKS 256

#define GK 1024            // pure fp16 GEMM: K = D
#define GM 8192            // B*S
#define GN 2048            // q rows then k rows
#define NCH (GK / 32)      // 32 K-chunks of 32

// ---------------------------------------------------------------------------
// Device scratch (allocation-free per harness rules)
// ---------------------------------------------------------------------------
__device__ __align__(256) __half g_A[(size_t)GM * GK];   // 16 MB
__device__ __align__(256) __half g_W[(size_t)GN * GK];   //  4 MB
// head-major projected Q (pre-scaled by 1/8) and K, fp16
__device__ __align__(256) __half g_Qh[(size_t)Bn * Hn * Sn * HDn];  // 16 MB
__device__ __align__(256) __half g_Kh[(size_t)Bn * Hn * Sn * HDn];

// ---------------------------------------------------------------------------
// Baseline-PTX helpers (no sm_103a-only features — harness targets compute_103)
// ---------------------------------------------------------------------------
__device__ __forceinline__ uint32_t smem_u32(const void* p) {
    uint32_t a;
    asm("{ .reg .u64 t; cvta.to.shared.u64 t, %1; cvt.u32.u64 %0, t; }"
        : "=r"(a) : "l"(p));
    return a;
}
__device__ __forceinline__ void cp16(uint32_t dst, const void* src) {
    asm volatile("cp.async.cg.shared.global [%0], [%1], 16;" :: "r"(dst), "l"(src));
}
#define CP_COMMIT() asm volatile("cp.async.commit_group;" ::: "memory")
#define CP_WAIT2()  asm volatile("cp.async.wait_group 2;" ::: "memory")
#define CP_WAIT1()  asm volatile("cp.async.wait_group 1;" ::: "memory")
#define CP_WAIT0()  asm volatile("cp.async.wait_group 0;" ::: "memory")

#define LDSM_X4(r, addr) \
    asm volatile("ldmatrix.sync.aligned.m8n8.x4.shared.b16 {%0,%1,%2,%3}, [%4];" \
        : "=r"((r)[0]), "=r"((r)[1]), "=r"((r)[2]), "=r"((r)[3]) : "r"(addr))

__device__ __forceinline__ void mma_f16(float* c, const uint32_t* a,
                                        const uint32_t* b) {
    asm volatile(
        "mma.sync.aligned.m16n8k16.row.col.f32.f16.f16.f32 "
        "{%0,%1,%2,%3}, {%4,%5,%6,%7}, {%8,%9}, {%0,%1,%2,%3};"
        : "+f"(c[0]), "+f"(c[1]), "+f"(c[2]), "+f"(c[3])
        : "r"(a[0]), "r"(a[1]), "r"(a[2]), "r"(a[3]), "r"(b[0]), "r"(b[1]));
}

// ---------------------------------------------------------------------------
// Fused cast kernel, 16 floats/thread:
//   blocks [0, 2048):    x -> fp16 g_A
//   blocks [2048, 2560): wq/wk -> fp16 g_W
// ---------------------------------------------------------------------------
__device__ __forceinline__ uint32_t pk2h(__half a, __half b) {
    return (uint32_t)__half_as_ushort(a) | ((uint32_t)__half_as_ushort(b) << 16);
}

__device__ __forceinline__ uint4 cast8(const float4 v0, const float4 v1) {
    float v[8] = {v0.x, v0.y, v0.z, v0.w, v1.x, v1.y, v1.z, v1.w};
    __half h[8];
    #pragma unroll
    for (int e = 0; e < 8; e++) h[e] = __float2half(v[e]);
    uint4 H = {pk2h(h[0], h[1]), pk2h(h[2], h[3]),
               pk2h(h[4], h[5]), pk2h(h[6], h[7])};
    return H;
}

__global__ __launch_bounds__(256) void cast_all(const float* __restrict__ x,
                                                const float* __restrict__ wq,
                                                const float* __restrict__ wk) {
    const int blk = blockIdx.x;
    if (blk < 2048) {
        size_t i = ((size_t)blk * 256 + threadIdx.x) * 16;
        float4 v0 = *(const float4*)(x + i);
        float4 v1 = *(const float4*)(x + i + 4);
        float4 v2 = *(const float4*)(x + i + 8);
        float4 v3 = *(const float4*)(x + i + 12);
        *(uint4*)(g_A + i)     = cast8(v0, v1);
        *(uint4*)(g_A + i + 8) = cast8(v2, v3);
    } else {
        size_t i = ((size_t)(blk - 2048) * 256 + threadIdx.x) * 16;
        size_t n = i >> 10, k = i & 1023;
        const float* src = (n < 1024) ? (wq + n * 1024 + k)
                                      : (wk + (n - 1024) * 1024 + k);
        float4 v0 = *(const float4*)src;
        float4 v1 = *(const float4*)(src + 4);
        float4 v2 = *(const float4*)(src + 8);
        float4 v3 = *(const float4*)(src + 12);
        *(uint4*)(g_W + i)     = cast8(v0, v1);
        *(uint4*)(g_W + i + 8) = cast8(v2, v3);
    }
}

// ---------------------------------------------------------------------------
// mma.sync fp16 GEMM (mainloop FROZEN — at legacy-HMMA ceiling):
//   C = fp16(x) . fp16(w)^T (+bias), K=1024
//   CTA 128x128, K-chunk 32, 4-stage cp.async pipeline, 2 CTA/SM.
//   Ride-along (DRAM idle under HMMA): zero-fill this CTA's out_w slice
//   EXCLUDING the diagonal 256-col band (attn writes it) + copy its 32 KB
//   slice of x into the output tuple.
//   Epilogue: +bias; Q: *0.125; fp16 cast; head-major write.
// ---------------------------------------------------------------------------
#define RS 80                      // smem row stride bytes (32 fp16 + pad)
#define STAGE (128 * RS * 2)       // A(10240) + B(10240) = 20480
#define GEMM_SMEM (4 * STAGE)      // 81920

__global__ __launch_bounds__(256, 2) void gemm_tc(
    const float* __restrict__ bq, const float* __restrict__ bk,
    const float* __restrict__ x,  float* __restrict__ out_x,
    float* __restrict__ out_w,    int do_copy)
{
    extern __shared__ char smem[];
    const uint32_t smb = smem_u32(smem);
    const int tid  = threadIdx.x;
    const int wid  = tid >> 5;
    const int lane = tid & 31;
    const int mw = wid & 3;        // m warp (32 rows)
    const int nw = wid >> 2;       // n warp (64 cols)
    const int bn = blockIdx.x;     // 0..15
    const int bm = blockIdx.y;     // 0..63

    float c[2][8][4];
    #pragma unroll
    for (int mt = 0; mt < 2; mt++)
        #pragma unroll
        for (int nt = 0; nt < 8; nt++)
            #pragma unroll
            for (int e = 0; e < 4; e++) c[mt][nt][e] = 0.f;

    const uint32_t a_base = (uint32_t)((mw * 32 + (lane & 15)) * RS + (lane >> 4) * 16);
    const uint32_t b_base = (uint32_t)(128 * RS +
        (nw * 64 + ((lane >> 4) & 1) * 8 + (lane & 7)) * RS + ((lane >> 3) & 1) * 16);

    auto stage = [&](int slot, int kc) {
        const uint32_t sb = smb + slot * STAGE;
        const size_t koff = (size_t)kc * 32;
        #pragma unroll
        for (int i = 0; i < 4; i++) {
            const int idx = tid + i * 256;      // 0..1023
            const int row = idx >> 2, cc = idx & 3;
            if (row < 128) {
                cp16(sb + row * RS + cc * 16,
                     g_A + (size_t)(bm * 128 + row) * GK + koff + cc * 8);
            } else {
                const int r2 = row - 128;
                cp16(sb + 128 * RS + r2 * RS + cc * 16,
                     g_W + (size_t)(bn * 128 + r2) * GK + koff + cc * 8);
            }
        }
    };

    #pragma unroll
    for (int s = 0; s < 3; s++) { stage(s, s); CP_COMMIT(); }

    // Ride-along stores while the prologue cp.asyncs land:
    //   zero-fill the out_w slice minus its diagonal band; copy the x slice.
    {
        const int cta = bm * 16 + bn;                // 0..1023, covers 8 rows
        // All 8 rows share one 256-token block: blk64 = (blk*256)/4 in float4s
        const int blk64 = ((((cta * 8) & (Sn - 1)) >> 8) << 6);
        const size_t rowbase = (size_t)cta * 4096;   // float4 index of row 0
        const float4 z = {0.f, 0.f, 0.f, 0.f};
        float4* zw = (float4*)out_w;
        #pragma unroll
        for (int i = 0; i < 14; i++) {               // 14*256 = 8 rows * 448
            const int idx = tid + i * 256;
            const int row = idx / 448, cc = idx % 448;
            const int c4 = cc + ((cc >= blk64) ? 64 : 0);  // skip diagonal band
            zw[rowbase + row * 512 + c4] = z;
        }
        if (do_copy) {
            const float4* src = (const float4*)x + (size_t)cta * 2048;
            float4* dst = (float4*)out_x + (size_t)cta * 2048;
            #pragma unroll
            for (int i = 0; i < 8; i++)
                dst[tid + i * 256] = src[tid + i * 256];
        }
    }

    for (int kc = 0; kc < NCH; kc++) {
        const uint32_t sb = smb + (kc & 3) * STAGE;
        CP_WAIT2();
        __syncthreads();
        if (kc + 3 < NCH) stage((kc + 3) & 3, kc + 3);
        CP_COMMIT();

        #pragma unroll
        for (int ks = 0; ks < 2; ks++) {
            uint32_t a0[4], a1[4], b0[4], b1[4], b2[4], b3[4];
            LDSM_X4(a0, sb + a_base + ks * 32);
            LDSM_X4(a1, sb + a_base + 16 * RS + ks * 32);
            LDSM_X4(b0, sb + b_base + ks * 32);
            LDSM_X4(b1, sb + b_base + 16 * RS + ks * 32);
            LDSM_X4(b2, sb + b_base + 32 * RS + ks * 32);
            LDSM_X4(b3, sb + b_base + 48 * RS + ks * 32);
            const uint32_t* bp[4] = {b0, b1, b2, b3};
            #pragma unroll
            for (int mt = 0; mt < 2; mt++) {
                const uint32_t* a = mt ? a1 : a0;
                #pragma unroll
                for (int nt = 0; nt < 8; nt++)
                    mma_f16(c[mt][nt], a, bp[nt >> 1] + (nt & 1) * 2);
            }
        }
    }

    // Epilogue: bias, (Q: *0.125), fp16 cast, head-major write
    const int nbase = (bn & 7) * 128 + nw * 64 + (lane & 3) * 2;   // 0..1023
    const bool isQ = (bn < 8);
    const float* bias = isQ ? bq : bk;
    __half* th = isQ ? g_Qh : g_Kh;
    const int hh = ((bn & 7) << 1) + nw;           // head (constant per thread)
    const float scl = isQ ? 0.125f : 1.0f;
    float2 bv[8];
    #pragma unroll
    for (int nt = 0; nt < 8; nt++)
        bv[nt] = *(const float2*)(bias + nbase + nt * 8);

    #pragma unroll
    for (int mt = 0; mt < 2; mt++) {
        #pragma unroll
        for (int h2 = 0; h2 < 2; h2++) {
            const int m = bm * 128 + mw * 32 + mt * 16 + h2 * 8 + (lane >> 2);
            const int bb = m >> 11, ss = m & 2047;
            const size_t rowoff = ((size_t)(bb * Hn + hh) * Sn + ss) * HDn
                                + (lane & 3) * 2;
            #pragma unroll
            for (int nt = 0; nt < 8; nt++) {
                float v0 = (c[mt][nt][h2 * 2 + 0] + bv[nt].x) * scl;
                float v1 = (c[mt][nt][h2 * 2 + 1] + bv[nt].y) * scl;
                *(__half2*)(th + rowoff + nt * 8) =
                    __halves2half2(__float2half(v0), __float2half(v1));
            }
        }
    }
}

// ---------------------------------------------------------------------------
// Tensor-core block-diagonal attention (validated FINAL form):
//   1-term scores (s = q_h . k_h), CTA = 64 q rows x 256 keys, 256 threads /
//   8 warps (2m x 4n, tile 32x64), grid (4 q-chunks, 8 blocks, 4 batches).
//   Fragments only — zero-fill and x-copy live in gemm_tc.
// ---------------------------------------------------------------------------
#define KHI 0
#define QHI 32768
#define ABUF 40960
#define SUMO (2 * ABUF)                       // row-sum scratch
#define ATTN_SMEM (SUMO + 4 * 64 * 4)         // 82,944

__global__ __launch_bounds__(256, 1) void attn_tc(float* __restrict__ out_w)
{
    extern __shared__ char smem[];
    const uint32_t smb = smem_u32(smem);
    float* sums = (float*)(smem + SUMO);

    const int tid  = threadIdx.x;
    const int wid  = tid >> 5;
    const int lane = tid & 31;
    const int nw = wid & 3;        // n warp: 64 keys
    const int mw = wid >> 2;       // m warp: 32 q rows
    const int b = blockIdx.z, blk = blockIdx.y, qc = blockIdx.x;
    const int srow = blk * BLKS + qc * 64;     // first q row (within batch)
    const int krow = blk * BLKS;               // first key row

    auto stage = [&](int buf, int h) {
        const size_t kbase = ((size_t)(b * Hn + h) * Sn + krow) * HDn;
        const size_t qbase = ((size_t)(b * Hn + h) * Sn + srow) * HDn;
        const uint32_t sb = smb + buf * ABUF;
        #pragma unroll
        for (int it = 0; it < 8; it++) {
            const int idx = tid + it * 256;          // 0..2047
            const int row = idx >> 3, ch = idx & 7;
            const uint32_t d = (uint32_t)(row * 128 + ((ch ^ (row & 7)) << 4));
            cp16(sb + KHI + d, g_Kh + kbase + row * HDn + ch * 8);
        }
        #pragma unroll
        for (int it = 0; it < 2; it++) {
            const int idx = tid + it * 256;          // 0..511
            const int row = idx >> 3, ch = idx & 7;
            const uint32_t d = (uint32_t)(row * 128 + ((ch ^ (row & 7)) << 4));
            cp16(sb + QHI + d, g_Qh + qbase + row * HDn + ch * 8);
        }
    };

    stage(0, 0); CP_COMMIT();

    float acc[2][8][4];
    #pragma unroll
    for (int mt = 0; mt < 2; mt++)
        #pragma unroll
        for (int nt = 0; nt < 8; nt++)
            #pragma unroll
            for (int e = 0; e < 4; e++) acc[mt][nt][e] = 0.f;

    for (int h = 0; h < Hn; h++) {
        if (h + 1 < Hn) { stage((h + 1) & 1, h + 1); CP_COMMIT(); CP_WAIT1(); }
        else            { CP_WAIT0(); }
        __syncthreads();
        const uint32_t sb = smb + (h & 1) * ABUF;

        float c[2][8][4];
        #pragma unroll
        for (int mt = 0; mt < 2; mt++)
            #pragma unroll
            for (int nt = 0; nt < 8; nt++)
                #pragma unroll
                for (int e = 0; e < 4; e++) c[mt][nt][e] = 0.f;

        #pragma unroll
        for (int ks = 0; ks < 4; ks++) {
            uint32_t a[2][4], bf[4][4];
            #pragma unroll
            for (int mt = 0; mt < 2; mt++) {
                const int row = mw * 32 + mt * 16 + (lane & 15);
                const int ci = 2 * ks + (lane >> 4);
                LDSM_X4(a[mt], sb + QHI + row * 128 + ((ci ^ (row & 7)) << 4));
            }
            #pragma unroll
            for (int nb = 0; nb < 4; nb++) {
                const int r = nw * 64 + nb * 16 + ((lane >> 4) & 1) * 8 + (lane & 7);
                const int ci = 2 * ks + ((lane >> 3) & 1);
                LDSM_X4(bf[nb], sb + KHI + r * 128 + ((ci ^ (r & 7)) << 4));
            }
            #pragma unroll
            for (int mt = 0; mt < 2; mt++)
                #pragma unroll
                for (int nt = 0; nt < 8; nt++)
                    mma_f16(c[mt][nt], a[mt], bf[nt >> 1] + (nt & 1) * 2);
        }

        // exp (scores pre-scaled via Q; no max-sub needed, |s| <~ 6)
        #pragma unroll
        for (int mt = 0; mt < 2; mt++)
            #pragma unroll
            for (int nt = 0; nt < 8; nt++)
                #pragma unroll
                for (int e = 0; e < 4; e++) c[mt][nt][e] = __expf(c[mt][nt][e]);

        // per-row partial sums over this warp's 64 keys -> smem
        #pragma unroll
        for (int mt = 0; mt < 2; mt++) {
            #pragma unroll
            for (int h2 = 0; h2 < 2; h2++) {
                float p = 0.f;
                #pragma unroll
                for (int nt = 0; nt < 8; nt++)
                    p += c[mt][nt][h2 * 2] + c[mt][nt][h2 * 2 + 1];
                p += __shfl_xor_sync(0xffffffffu, p, 1);
                p += __shfl_xor_sync(0xffffffffu, p, 2);
                const int lr = mw * 32 + mt * 16 + h2 * 8 + (lane >> 2);
                if ((lane & 3) == 0) sums[nw * 64 + lr] = p;
            }
        }
        __syncthreads();

        #pragma unroll
        for (int mt = 0; mt < 2; mt++) {
            #pragma unroll
            for (int h2 = 0; h2 < 2; h2++) {
                const int lr = mw * 32 + mt * 16 + h2 * 8 + (lane >> 2);
                const float denom = sums[lr] + sums[64 + lr]
                                  + sums[128 + lr] + sums[192 + lr];
                const float inv = (1.f / 16.f) / denom;
                #pragma unroll
                for (int nt = 0; nt < 8; nt++) {
                    acc[mt][nt][h2 * 2]     += c[mt][nt][h2 * 2] * inv;
                    acc[mt][nt][h2 * 2 + 1] += c[mt][nt][h2 * 2 + 1] * inv;
                }
            }
        }
    }

    // fragment store: out_w[b][srow+lr][blk*256 + nw*64 + nt*8 + (lane&3)*2]
    #pragma unroll
    for (int mt = 0; mt < 2; mt++) {
        #pragma unroll
        for (int h2 = 0; h2 < 2; h2++) {
            const int lr = mw * 32 + mt * 16 + h2 * 8 + (lane >> 2);
            const size_t base = ((size_t)(b * Sn + srow + lr)) * Sn
                              + blk * BLKS + nw * 64 + (lane & 3) * 2;
            #pragma unroll
            for (int nt = 0; nt < 8; nt++) {
                float2 v = {acc[mt][nt][h2 * 2], acc[mt][nt][h2 * 2 + 1]};
                *(float2*)(out_w + base + nt * 8) = v;
            }
        }
    }
}

// ---------------------------------------------------------------------------
extern "C" void kernel_launch(void* const* d_in, const int* in_sizes, int n_in,
                              void* d_out, int out_size)
{
    const float* x  = (const float*)d_in[0];
    const float* wq = (const float*)d_in[1];
    const float* wk = (const float*)d_in[2];
    const float* bq = (const float*)d_in[3];
    const float* bk = (const float*)d_in[4];
    float* out = (float*)d_out;

    const size_t x_elems = (size_t)Bn * Sn * Dn;   //  8,388,608
    const size_t w_elems = (size_t)Bn * Sn * Sn;   // 16,777,216

    float* out_w;
    int do_copy;
    if ((size_t)out_size >= x_elems + w_elems) {
        out_w = out + x_elems;
        do_copy = 1;
    } else {
        out_w = out;
        do_copy = 0;
    }

    // fp16 casts (16 floats/thread)
    cast_all<<<2560, 256>>>(x, wq, wk);

    // mma.sync fp16 projection GEMM (128x128, 2 CTA/SM, K=1024)
    // + ride-along diagonal-skipping zero-fill of out_w and x->out copy
    cudaFuncSetAttribute(gemm_tc, cudaFuncAttributeMaxDynamicSharedMemorySize,
                         GEMM_SMEM);
    dim3 ggrid(16, 64);
    gemm_tc<<<ggrid, 256, GEMM_SMEM>>>(bq, bk, x, out, out_w, do_copy);

    // tensor-core block-diagonal attention (fragments only)
    cudaFuncSetAttribute(attn_tc, cudaFuncAttributeMaxDynamicSharedMemorySize,
                         ATTN_SMEM);
    dim3 agrid(4, NBLK, Bn);
    attn_tc<<<agrid, 256, ATTN_SMEM>>>(out_w);
}